// round 16
// baseline (speedup 1.0000x reference)
#include <cuda_runtime.h>
#include <math.h>
#include <stdint.h>

// Problem constants (fixed by setup_inputs)
#define E_TOT   32768          // B*N*K = 1*1024*32
#define EDGE_D  32
#define MID_D   64
#define RAD_OUT 3072           // NC_OUT * RDIM

// Scratch (device globals; no allocations)
__device__ float g_W3T[RAD_OUT * MID_D];     // fragment order [rb][j][lane][16], 3 MB
__device__ float g_tmp[E_TOT * 32 * 12];     // tmp[e][rb][rl*4+m], 50 MB

#define BSTRIDE  20                          // floats per lane chunk (80 B)
#define BBUF     (12 * 32 * BSTRIDE)         // 7680 floats per B stage

// dynamic SMEM layout (floats)
#define SCR    15360                         // per-warp scratch base (after 2 B bufs)
#define SCRW   2176                          // 32 rows * 68 floats per warp
#define W1OFF  32768                         // SCR + 8*SCRW = 32768
#define W2OFF  34816
#define BIOFF  38912                         // b1,g1,be1,b2,g2,be2 (6*64)
#define SMEMF  39296                         // total floats (157184 B)

__device__ __forceinline__ float gelu_exact(float x) {
    return 0.5f * x * (1.0f + erff(x * 0.70710678118654752f));
}
__device__ __forceinline__ float tf32_rna(float x) {
    uint32_t u;
    asm("cvt.rna.tf32.f32 %0, %1;" : "=r"(u) : "f"(x));
    return __uint_as_float(u);
}
__device__ __forceinline__ uint32_t smem_u32(const void* p) {
    uint32_t a;
    asm("{ .reg .u64 t; cvta.to.shared.u64 t, %1; cvt.u32.u64 %0, t; }"
        : "=r"(a) : "l"(p));
    return a;
}
__device__ __forceinline__ void cp16(uint32_t daddr, const float* src) {
    asm volatile("cp.async.cg.shared.global [%0], [%1], 16;"
                 :: "r"(daddr), "l"(src));
}
__device__ __forceinline__ void mma_tf32(
    float& d0, float& d1, float& d2, float& d3,
    uint32_t a0, uint32_t a1, uint32_t a2, uint32_t a3,
    uint32_t b0, uint32_t b1)
{
    asm volatile(
        "mma.sync.aligned.m16n8k8.row.col.f32.tf32.tf32.f32 "
        "{%0,%1,%2,%3}, {%4,%5,%6,%7}, {%8,%9}, {%0,%1,%2,%3};"
        : "+f"(d0), "+f"(d1), "+f"(d2), "+f"(d3)
        : "r"(a0), "r"(a1), "r"(a2), "r"(a3), "r"(b0), "r"(b1));
}

// ---------------------------------------------------------------------------
// Kernel 0: W3 -> fragment-ordered tf32 W3T.
// element idx = ((rb*12 + j)*32 + lane)*16 + (ks*2 + half)
//   holds B[n=j*8+g][k=ks*8+q+half*4] for n = rloc*32+o, r = rb*3+rloc.
// ---------------------------------------------------------------------------
__global__ __launch_bounds__(256) void k_w3t(const float* __restrict__ W3) {
    int e = blockIdx.x * 256 + threadIdx.x;       // 0 .. 196607
    int pos  = e & 15;
    int lane = (e >> 4) & 31;
    int t    = e >> 9;                            // rb*12 + j
    int j = t % 12, rb = t / 12;
    int g = lane >> 2, q = lane & 3;
    int ks = pos >> 1, half = pos & 1;
    int n = j * 8 + g;
    int rloc = n >> 5, o = n & 31;
    int k = ks * 8 + q + half * 4;
    g_W3T[e] = tf32_rna(W3[k * RAD_OUT + o * 96 + rb * 3 + rloc]);
}

// ---------------------------------------------------------------------------
// Fused kernel: thread-per-edge MLP prologue + tf32 mma.sync GEMM mainloop
// with fused tmp contraction. CTA = 256 edges, 256 threads = 8 warps x 32.
// ---------------------------------------------------------------------------
__global__ void __launch_bounds__(256, 1) k_main(
    const float* __restrict__ edges, const float* __restrict__ feats,
    const float* __restrict__ basis,
    const float* __restrict__ W1, const float* __restrict__ b1,
    const float* __restrict__ g1, const float* __restrict__ be1,
    const float* __restrict__ W2, const float* __restrict__ b2,
    const float* __restrict__ g2, const float* __restrict__ be2,
    float* __restrict__ out)
{
    extern __shared__ float S[];
    int tid = threadIdx.x, w = tid >> 5, lane = tid & 31;
    int g = lane >> 2, q = lane & 3;
    int ew = blockIdx.x * 256 + w * 32;
    int e  = blockIdx.x * 256 + tid;      // this thread's MLP edge
    uint32_t sb = smem_u32(S);

    // ---- issue B stage-0 prefetch immediately (overlaps MLP prologue) ----
#pragma unroll
    for (int i = 0; i < 6; i++) {
        int c = tid + 256 * i;
        cp16(sb + (((c >> 2) * BSTRIDE + (c & 3) * 4) << 2), g_W3T + c * 4);
    }
    asm volatile("cp.async.commit_group;" ::: "memory");

    // ---- stage MLP weights to SMEM ----
    for (int i = tid; i < 2048; i += 256) S[W1OFF + i] = W1[i];
    for (int i = tid; i < 4096; i += 256) S[W2OFF + i] = W2[i];
    if (tid < 64) {
        S[BIOFF + tid]       = b1[tid];  S[BIOFF + 64 + tid]  = g1[tid];
        S[BIOFF + 128 + tid] = be1[tid]; S[BIOFF + 192 + tid] = b2[tid];
        S[BIOFF + 256 + tid] = g2[tid];  S[BIOFF + 320 + tid] = be2[tid];
    }
    __syncthreads();

    float* scr = S + SCR + w * SCRW + lane * 68;  // per-thread 68-float row

    // ---- load x(32) into scratch ----
    {
        const float4* xg = (const float4*)(edges + (size_t)e * EDGE_D);
#pragma unroll
        for (int i = 0; i < 8; i++) {
            float4 v = xg[i];
            scr[i * 4] = v.x; scr[i * 4 + 1] = v.y;
            scr[i * 4 + 2] = v.z; scr[i * 4 + 3] = v.w;
        }
    }

    // ---- layer 1: h[j] = b1 + sum_i x[i] * W1[i][j] ----
    float h[64];
#pragma unroll
    for (int j = 0; j < 64; j++) h[j] = S[BIOFF + j];
#pragma unroll 4
    for (int i = 0; i < 32; i++) {
        float xi = scr[i];
        const float4* wr = (const float4*)(S + W1OFF + i * 64);
#pragma unroll
        for (int j4 = 0; j4 < 16; j4++) {
            float4 wv = wr[j4];
            h[j4 * 4 + 0] = fmaf(xi, wv.x, h[j4 * 4 + 0]);
            h[j4 * 4 + 1] = fmaf(xi, wv.y, h[j4 * 4 + 1]);
            h[j4 * 4 + 2] = fmaf(xi, wv.z, h[j4 * 4 + 2]);
            h[j4 * 4 + 3] = fmaf(xi, wv.w, h[j4 * 4 + 3]);
        }
    }
    // LN stats (4-way interleaved tree)
    {
        float s0 = 0.f, s1 = 0.f, s2 = 0.f, s3 = 0.f;
#pragma unroll
        for (int j4 = 0; j4 < 16; j4++) {
            s0 += h[j4 * 4]; s1 += h[j4 * 4 + 1];
            s2 += h[j4 * 4 + 2]; s3 += h[j4 * 4 + 3];
        }
        float mu = (s0 + s1 + s2 + s3) * (1.0f / 64.0f);
        float v0 = 0.f, v1 = 0.f, v2 = 0.f, v3 = 0.f;
#pragma unroll
        for (int j4 = 0; j4 < 16; j4++) {
            float d0 = h[j4 * 4] - mu, d1 = h[j4 * 4 + 1] - mu;
            float d2 = h[j4 * 4 + 2] - mu, d3 = h[j4 * 4 + 3] - mu;
            v0 = fmaf(d0, d0, v0); v1 = fmaf(d1, d1, v1);
            v2 = fmaf(d2, d2, v2); v3 = fmaf(d3, d3, v3);
        }
        float inv = rsqrtf((v0 + v1 + v2 + v3) * (1.0f / 64.0f) + 1e-5f);
#pragma unroll
        for (int j = 0; j < 64; j++) scr[j] = (h[j] - mu) * inv;
    }
    // gamma/beta + GELU (dynamic-index loop; tiny code)
    for (int j = 0; j < 64; j++)
        scr[j] = gelu_exact(scr[j] * S[BIOFF + 64 + j] + S[BIOFF + 128 + j]);

    // ---- layer 2: h2[j] = b2 + sum_i h1[i] * W2[i][j] ----
#pragma unroll
    for (int j = 0; j < 64; j++) h[j] = S[BIOFF + 192 + j];
#pragma unroll 4
    for (int i = 0; i < 64; i++) {
        float xi = scr[i];
        const float4* wr = (const float4*)(S + W2OFF + i * 64);
#pragma unroll
        for (int j4 = 0; j4 < 16; j4++) {
            float4 wv = wr[j4];
            h[j4 * 4 + 0] = fmaf(xi, wv.x, h[j4 * 4 + 0]);
            h[j4 * 4 + 1] = fmaf(xi, wv.y, h[j4 * 4 + 1]);
            h[j4 * 4 + 2] = fmaf(xi, wv.z, h[j4 * 4 + 2]);
            h[j4 * 4 + 3] = fmaf(xi, wv.w, h[j4 * 4 + 3]);
        }
    }
    {
        float s0 = 0.f, s1 = 0.f, s2 = 0.f, s3 = 0.f;
#pragma unroll
        for (int j4 = 0; j4 < 16; j4++) {
            s0 += h[j4 * 4]; s1 += h[j4 * 4 + 1];
            s2 += h[j4 * 4 + 2]; s3 += h[j4 * 4 + 3];
        }
        float mu = (s0 + s1 + s2 + s3) * (1.0f / 64.0f);
        float v0 = 0.f, v1 = 0.f, v2 = 0.f, v3 = 0.f;
#pragma unroll
        for (int j4 = 0; j4 < 16; j4++) {
            float d0 = h[j4 * 4] - mu, d1 = h[j4 * 4 + 1] - mu;
            float d2 = h[j4 * 4 + 2] - mu, d3 = h[j4 * 4 + 3] - mu;
            v0 = fmaf(d0, d0, v0); v1 = fmaf(d1, d1, v1);
            v2 = fmaf(d2, d2, v2); v3 = fmaf(d3, d3, v3);
        }
        float inv = rsqrtf((v0 + v1 + v2 + v3) * (1.0f / 64.0f) + 1e-5f);
#pragma unroll
        for (int j = 0; j < 64; j++) scr[j] = (h[j] - mu) * inv;
    }
    // gamma/beta + GELU + tf32 round: final h2 stays in SMEM scratch
    for (int j = 0; j < 64; j++)
        scr[j] = tf32_rna(gelu_exact(scr[j] * S[BIOFF + 256 + j]
                                     + S[BIOFF + 320 + j]));

    // ---- tmp[e][i][rl*4+m] = feats[e,i,:] @ basis[e,:,rl*3+m] -> gmem ----
    {
        float bv[27];
        const float* bs = basis + (size_t)e * 27;
#pragma unroll
        for (int c = 0; c < 27; c++) bv[c] = __ldg(&bs[c]);
        const float* fe = feats + (size_t)e * 96;
        float* tb = g_tmp + (size_t)e * 384;
#pragma unroll 2
        for (int i = 0; i < 32; i++) {
            float f0 = __ldg(&fe[i * 3 + 0]);
            float f1 = __ldg(&fe[i * 3 + 1]);
            float f2 = __ldg(&fe[i * 3 + 2]);
            float v[9];
#pragma unroll
            for (int c = 0; c < 9; c++)
                v[c] = fmaf(f0, bv[c], fmaf(f1, bv[9 + c], f2 * bv[18 + c]));
            float4* tp = (float4*)(tb + i * 12);
            tp[0] = make_float4(v[0], v[1], v[2], 0.0f);
            tp[1] = make_float4(v[3], v[4], v[5], 0.0f);
            tp[2] = make_float4(v[6], v[7], v[8], 0.0f);
        }
    }
    __syncthreads();   // h2 scratch + g_tmp visible CTA-wide

    // ---- A fragments from SMEM scratch (rows = warp's 32 edges) ----
    const float* hb = S + SCR + w * SCRW;
    uint32_t a[8][8];
#pragma unroll
    for (int ks = 0; ks < 8; ks++) {
        int c0 = ks * 8 + q;
        a[ks][0] = __float_as_uint(hb[g * 68 + c0]);
        a[ks][1] = __float_as_uint(hb[(g + 8) * 68 + c0]);
        a[ks][2] = __float_as_uint(hb[g * 68 + c0 + 4]);
        a[ks][3] = __float_as_uint(hb[(g + 8) * 68 + c0 + 4]);
        a[ks][4] = __float_as_uint(hb[(g + 16) * 68 + c0]);
        a[ks][5] = __float_as_uint(hb[(g + 24) * 68 + c0]);
        a[ks][6] = __float_as_uint(hb[(g + 16) * 68 + c0 + 4]);
        a[ks][7] = __float_as_uint(hb[(g + 24) * 68 + c0 + 4]);
    }

    float acc[4][8][3];
#pragma unroll
    for (int s = 0; s < 4; s++)
#pragma unroll
        for (int i = 0; i < 8; i++)
#pragma unroll
            for (int m = 0; m < 3; m++) acc[s][i][m] = 0.0f;

    const float4* tp0 = (const float4*)g_tmp + (size_t)(ew + g) * 96;
    const float4* tp1 = (const float4*)g_tmp + (size_t)(ew + g + 8) * 96;
    const float4* tp2 = (const float4*)g_tmp + (size_t)(ew + g + 16) * 96;
    const float4* tp3 = (const float4*)g_tmp + (size_t)(ew + g + 24) * 96;

    for (int rb = 0; rb < 32; rb++) {
        asm volatile("cp.async.wait_group 0;" ::: "memory");
        __syncthreads();                 // stage rb visible; other buf free
        if (rb < 31) {
            const float* src = g_W3T + (rb + 1) * 6144;
            uint32_t dbase = sb + ((rb + 1) & 1) * (BBUF * 4);
#pragma unroll
            for (int i = 0; i < 6; i++) {
                int c = tid + 256 * i;
                cp16(dbase + (((c >> 2) * BSTRIDE + (c & 3) * 4) << 2),
                     src + c * 4);
            }
            asm volatile("cp.async.commit_group;" ::: "memory");
        }

        const float* bbase = S + (rb & 1) * BBUF;
#pragma unroll
        for (int rl = 0; rl < 3; rl++) {
            float4 t0 = tp0[rb * 3 + rl], t1 = tp1[rb * 3 + rl];
            float4 t2 = tp2[rb * 3 + rl], t3 = tp3[rb * 3 + rl];
#pragma unroll
            for (int jm = 0; jm < 4; jm++) {
                int j = rl * 4 + jm;
                const float4* bp =
                    (const float4*)(bbase + (j * 32 + lane) * BSTRIDE);
                float4 f0 = bp[0], f1 = bp[1], f2 = bp[2], f3 = bp[3];
                uint32_t bf[16] = {
                    __float_as_uint(f0.x), __float_as_uint(f0.y),
                    __float_as_uint(f0.z), __float_as_uint(f0.w),
                    __float_as_uint(f1.x), __float_as_uint(f1.y),
                    __float_as_uint(f1.z), __float_as_uint(f1.w),
                    __float_as_uint(f2.x), __float_as_uint(f2.y),
                    __float_as_uint(f2.z), __float_as_uint(f2.w),
                    __float_as_uint(f3.x), __float_as_uint(f3.y),
                    __float_as_uint(f3.z), __float_as_uint(f3.w)};

                float d0 = 0.f, d1 = 0.f, d2 = 0.f, d3 = 0.f;
                float u0 = 0.f, u1 = 0.f, u2 = 0.f, u3 = 0.f;
                float p0 = 0.f, p1 = 0.f, p2 = 0.f, p3 = 0.f;
                float v0 = 0.f, v1 = 0.f, v2 = 0.f, v3 = 0.f;
#pragma unroll
                for (int ks = 0; ks < 8; ks += 2) {
                    mma_tf32(d0, d1, d2, d3,
                             a[ks][0], a[ks][1], a[ks][2], a[ks][3],
                             bf[ks * 2], bf[ks * 2 + 1]);
                    mma_tf32(p0, p1, p2, p3,
                             a[ks][4], a[ks][5], a[ks][6], a[ks][7],
                             bf[ks * 2], bf[ks * 2 + 1]);
                    mma_tf32(u0, u1, u2, u3,
                             a[ks + 1][0], a[ks + 1][1], a[ks + 1][2], a[ks + 1][3],
                             bf[ks * 2 + 2], bf[ks * 2 + 3]);
                    mma_tf32(v0, v1, v2, v3,
                             a[ks + 1][4], a[ks + 1][5], a[ks + 1][6], a[ks + 1][7],
                             bf[ks * 2 + 2], bf[ks * 2 + 3]);
                }
                d0 += u0; d1 += u1; d2 += u2; d3 += u3;
                p0 += v0; p1 += v1; p2 += v2; p3 += v3;

                int c0 = jm * 2, c1 = jm * 2 + 1;
                acc[0][c0][0] = fmaf(d0, t0.x, acc[0][c0][0]);
                acc[0][c0][1] = fmaf(d0, t0.y, acc[0][c0][1]);
                acc[0][c0][2] = fmaf(d0, t0.z, acc[0][c0][2]);
                acc[0][c1][0] = fmaf(d1, t0.x, acc[0][c1][0]);
                acc[0][c1][1] = fmaf(d1, t0.y, acc[0][c1][1]);
                acc[0][c1][2] = fmaf(d1, t0.z, acc[0][c1][2]);
                acc[1][c0][0] = fmaf(d2, t1.x, acc[1][c0][0]);
                acc[1][c0][1] = fmaf(d2, t1.y, acc[1][c0][1]);
                acc[1][c0][2] = fmaf(d2, t1.z, acc[1][c0][2]);
                acc[1][c1][0] = fmaf(d3, t1.x, acc[1][c1][0]);
                acc[1][c1][1] = fmaf(d3, t1.y, acc[1][c1][1]);
                acc[1][c1][2] = fmaf(d3, t1.z, acc[1][c1][2]);
                acc[2][c0][0] = fmaf(p0, t2.x, acc[2][c0][0]);
                acc[2][c0][1] = fmaf(p0, t2.y, acc[2][c0][1]);
                acc[2][c0][2] = fmaf(p0, t2.z, acc[2][c0][2]);
                acc[2][c1][0] = fmaf(p1, t2.x, acc[2][c1][0]);
                acc[2][c1][1] = fmaf(p1, t2.y, acc[2][c1][1]);
                acc[2][c1][2] = fmaf(p1, t2.z, acc[2][c1][2]);
                acc[3][c0][0] = fmaf(p2, t3.x, acc[3][c0][0]);
                acc[3][c0][1] = fmaf(p2, t3.y, acc[3][c0][1]);
                acc[3][c0][2] = fmaf(p2, t3.z, acc[3][c0][2]);
                acc[3][c1][0] = fmaf(p3, t3.x, acc[3][c1][0]);
                acc[3][c1][1] = fmaf(p3, t3.y, acc[3][c1][1]);
                acc[3][c1][2] = fmaf(p3, t3.z, acc[3][c1][2]);
            }
        }
    }

    // Store: slot s -> edge ew + g + s*8; o = jm*8 + 2q (+1)
#pragma unroll
    for (int s = 0; s < 4; s++) {
        float* op = out + (size_t)(ew + g + s * 8) * 96;
#pragma unroll
        for (int jm = 0; jm < 4; jm++) {
            float* p = op + (jm * 8 + 2 * q) * 3;
            float2* p2 = (float2*)p;
            p2[0] = make_float2(acc[s][jm * 2][0],     acc[s][jm * 2][1]);
            p2[1] = make_float2(acc[s][jm * 2][2],     acc[s][jm * 2 + 1][0]);
            p2[2] = make_float2(acc[s][jm * 2 + 1][1], acc[s][jm * 2 + 1][2]);
        }
    }
}

// ---------------------------------------------------------------------------
extern "C" void kernel_launch(void* const* d_in, const int* in_sizes, int n_in,
                              void* d_out, int out_size)
{
    const float* edges = (const float*)d_in[0];
    const float* feats = (const float*)d_in[1];
    const float* basis = (const float*)d_in[2];
    const float* W1    = (const float*)d_in[3];
    const float* b1    = (const float*)d_in[4];
    const float* g1    = (const float*)d_in[5];
    const float* be1   = (const float*)d_in[6];
    const float* W2    = (const float*)d_in[7];
    const float* b2    = (const float*)d_in[8];
    const float* g2    = (const float*)d_in[9];
    const float* be2   = (const float*)d_in[10];
    const float* W3    = (const float*)d_in[11];
    float* out = (float*)d_out;

    // Host-side attributes (not stream ops; capture-safe, no allocation)
    cudaFuncSetAttribute(k_main, cudaFuncAttributeMaxDynamicSharedMemorySize,
                         SMEMF * 4);
    cudaFuncSetAttribute(k_main,
                         cudaFuncAttributePreferredSharedMemoryCarveout, 100);

    k_w3t<<<(RAD_OUT * MID_D) / 256, 256>>>(W3);
    k_main<<<E_TOT / 256, 256, SMEMF * 4>>>(edges, feats, basis,
                                            W1, b1, g1, be1,
                                            W2, b2, g2, be2, out);
}